// round 5
// baseline (speedup 1.0000x reference)
#include <cuda_runtime.h>

// One level of separable wavelet FB (maxflat), periodic extension, ds-by-2.
// x: [24, 1024, 1024] f32  ->  out: [4, 24, 512, 512] f32  (bands LL,LH,HL,HH)
//
// Fully fused: each block computes a TI x TJ output tile (all 4 bands) of one
// image. Phase 1: load (2*TI+6) x (2*TJ+6) input halo tile to smem (float4,
// periodic wrap via &1023). Phase 2: horizontal filtering -> L/H in smem.
// Phase 3: vertical filtering -> 4 coalesced band stores.

#define TI 16
#define TJ 64
#define IN_ROWS 38        // 2*TI + 6
#define IN_PITCH 136      // 2*TJ + 6 = 134, padded to multiple of 4 (float4 rows)
#define NTHREADS 256

__global__ __launch_bounds__(NTHREADS, 1)
void wfb2dec_kernel(const float* __restrict__ x, float* __restrict__ out)
{
    __shared__ float s_in[IN_ROWS][IN_PITCH];
    __shared__ float s_L[IN_ROWS][TJ];
    __shared__ float s_H[IN_ROWS][TJ];

    // Symmetric filters (exact values from the reference maxflat construction)
    const float h0 = 0.125f;
    const float h1c = 0.35355339059327378f;
    const float h2 = 1.25f;
    // h  = {h0, h1c, h2, h1c, h0}, ext = 2
    const float g0 = 0.025888347648318447f;
    const float g1 = 0.07322330470336313f;
    const float g2 = -0.06878156646177090f;
    const float g3 = -0.85355339059327373f;
    // h1 = {g0, g1, g2, g3, g2, g1, g0}, ext = 4

    const int tid = threadIdx.x;
    const int j0  = blockIdx.x * TJ;     // output col base (0..511)
    const int i0  = blockIdx.y * TI;     // output row base (0..511)
    const int img = blockIdx.z;          // 0..23

    const float* __restrict__ src = x + (size_t)img * (1024u * 1024u);
    const int base_row = 2 * i0 - 4;     // col-filter extent 4 (7-tap)
    const int base_col = 2 * j0 - 4;     // row-filter extent 4 (7-tap)

    // ---- Phase 1: load input halo tile (38 rows x 136 cols as float4) ----
    // base_col = 128*bx - 4 -> always ≡ 0 (mod 4), so float4 never straddles
    // the periodic wrap (wrap offsets are multiples of 4, all within [0,1024)).
    for (int idx = tid; idx < IN_ROWS * (IN_PITCH / 4); idx += NTHREADS) {
        int r  = idx / (IN_PITCH / 4);
        int c4 = idx - r * (IN_PITCH / 4);
        int gr = (base_row + r) & 1023;
        int gc = (base_col + c4 * 4) & 1023;
        float4 v = *reinterpret_cast<const float4*>(src + (size_t)gr * 1024 + gc);
        *reinterpret_cast<float4*>(&s_in[r][c4 * 4]) = v;
    }
    __syncthreads();

    // ---- Phase 2: horizontal filter, downsample by 2 in columns ----
    // x_L[j] = sum_k h[k]  * x[2j+k-2]  -> local t = 2j+2+k, k in [0,5)
    // x_H[j] = sum_k h1[k] * x[2j+k-4]  -> local t = 2j+k,   k in [0,7)
    for (int idx = tid; idx < IN_ROWS * TJ; idx += NTHREADS) {
        int r = idx >> 6;
        int j = idx & 63;
        const float* p = &s_in[r][2 * j];
        float a0 = p[0], a1 = p[1], a2 = p[2], a3 = p[3];
        float a4 = p[4], a5 = p[5], a6 = p[6];
        s_H[r][j] = g0 * (a0 + a6) + g1 * (a1 + a5) + g2 * (a2 + a4) + g3 * a3;
        s_L[r][j] = h0 * (a2 + a6) + h1c * (a3 + a5) + h2 * a4;
    }
    __syncthreads();

    // ---- Phase 3: vertical filter, downsample by 2 in rows; 4 band stores ----
    const int j  = tid & 63;
    const int ib = tid >> 6;             // 0..3
    const size_t bandStride = (size_t)24 * 512 * 512;
    const size_t imgOff = (size_t)img * (512u * 512u);

    #pragma unroll
    for (int ii = 0; ii < TI / 4; ii++) {
        int i = ib + ii * 4;             // 0..15
        int r = 2 * i;                   // local row base; rows r..r+6 used
        float l0 = s_L[r    ][j], l1 = s_L[r + 1][j], l2 = s_L[r + 2][j];
        float l3 = s_L[r + 3][j], l4 = s_L[r + 4][j], l5 = s_L[r + 5][j];
        float l6 = s_L[r + 6][j];
        float q0 = s_H[r    ][j], q1 = s_H[r + 1][j], q2 = s_H[r + 2][j];
        float q3 = s_H[r + 3][j], q4 = s_H[r + 4][j], q5 = s_H[r + 5][j];
        float q6 = s_H[r + 6][j];

        float LL = h0 * (l2 + l6) + h1c * (l3 + l5) + h2 * l4;
        float LH = g0 * (l0 + l6) + g1 * (l1 + l5) + g2 * (l2 + l4) + g3 * l3;
        float HL = h0 * (q2 + q6) + h1c * (q3 + q5) + h2 * q4;
        float HH = g0 * (q0 + q6) + g1 * (q1 + q5) + g2 * (q2 + q4) + g3 * q3;

        size_t o = imgOff + (size_t)(i0 + i) * 512 + (j0 + j);
        out[o                 ] = LL;
        out[o +     bandStride] = LH;
        out[o + 2 * bandStride] = HL;
        out[o + 3 * bandStride] = HH;
    }
}

extern "C" void kernel_launch(void* const* d_in, const int* in_sizes, int n_in,
                              void* d_out, int out_size)
{
    const float* x = (const float*)d_in[0];
    float* out = (float*)d_out;
    dim3 grid(512 / TJ, 512 / TI, 24);   // (8, 32, 24)
    wfb2dec_kernel<<<grid, NTHREADS>>>(x, out);
}

// round 6
// speedup vs baseline: 1.1940x; 1.1940x over previous
#include <cuda_runtime.h>

// One level of separable wavelet FB (maxflat), periodic extension, ds-by-2.
// x: [24, 1024, 1024] f32  ->  out: [4, 24, 512, 512] f32  (bands LL,LH,HL,HH)
//
// Phase A: horizontal filter straight from GMEM (float2 loads, periodic wrap),
//          writing L/H rows to smem. No input staging tile (kills the 2-way
//          bank-conflicted stride-2 LDS pass of the previous version).
// Phase B: vertical filter with a 7-row register window slid by 2 across
//          4 consecutive output rows per thread (26 LDS instead of 56).

#define TI 16
#define TJ 64
#define IN_ROWS 38        // 2*TI + 6
#define NTHREADS 256

__global__ __launch_bounds__(NTHREADS, 6)
void wfb2dec_kernel(const float* __restrict__ x, float* __restrict__ out)
{
    __shared__ float s_L[IN_ROWS][TJ];
    __shared__ float s_H[IN_ROWS][TJ];

    // Symmetric filters (exact values from the reference maxflat construction)
    const float h0  = 0.125f;
    const float h1c = 0.35355339059327378f;
    const float h2  = 1.25f;
    // h  = {h0, h1c, h2, h1c, h0}, ext = 2
    const float g0 = 0.025888347648318447f;
    const float g1 = 0.07322330470336313f;
    const float g2 = -0.06878156646177090f;
    const float g3 = -0.85355339059327373f;
    // h1 = {g0, g1, g2, g3, g2, g1, g0}, ext = 4

    const int tid = threadIdx.x;
    const int j0  = blockIdx.x * TJ;     // output col base (0..511)
    const int i0  = blockIdx.y * TI;     // output row base (0..511)
    const int img = blockIdx.z;          // 0..23

    const float* __restrict__ src = x + (size_t)img * (1024u * 1024u);
    const int base_row = 2 * i0 - 4;     // 7-tap vertical extent
    const int base_col = 2 * j0 - 4;     // 7-tap horizontal extent

    // ---- Phase A: horizontal filter + ds2, GMEM -> smem L/H ----
    // Output col J = j0+j needs input cols (base_col + 2j + t), t=0..6.
    // base_col and 2j are even -> every float2 (pair) sits inside one row and
    // never straddles the periodic wrap; wrap applied per pair via &1023.
    for (int idx = tid; idx < IN_ROWS * TJ; idx += NTHREADS) {
        int r = idx >> 6;
        int j = idx & 63;
        int gr = (base_row + r) & 1023;
        const float* __restrict__ row = src + (size_t)gr * 1024;
        int c0 = (base_col + 2 * j) & 1023;
        int c2 = (c0 + 2) & 1023;
        int c4 = (c0 + 4) & 1023;
        int c6 = (c0 + 6) & 1023;
        float2 v0 = *reinterpret_cast<const float2*>(row + c0);
        float2 v1 = *reinterpret_cast<const float2*>(row + c2);
        float2 v2 = *reinterpret_cast<const float2*>(row + c4);
        float2 v3 = *reinterpret_cast<const float2*>(row + c6);
        float a0 = v0.x, a1 = v0.y, a2 = v1.x, a3 = v1.y;
        float a4 = v2.x, a5 = v2.y, a6 = v3.x;
        s_H[r][j] = g0 * (a0 + a6) + g1 * (a1 + a5) + g2 * (a2 + a4) + g3 * a3;
        s_L[r][j] = h0 * (a2 + a6) + h1c * (a3 + a5) + h2 * a4;
    }
    __syncthreads();

    // ---- Phase B: vertical filter + ds2, sliding 7-row register window ----
    const int j  = tid & 63;
    const int ib = tid >> 6;             // 0..3 -> output rows ib*4 .. ib*4+3
    const int rb = 8 * ib;               // local row base (uses rows rb..rb+12)
    const size_t bandStride = (size_t)24 * 512 * 512;
    const size_t imgOff = (size_t)img * (512u * 512u);

    float l0 = s_L[rb    ][j], l1 = s_L[rb + 1][j], l2 = s_L[rb + 2][j];
    float l3 = s_L[rb + 3][j], l4 = s_L[rb + 4][j], l5 = s_L[rb + 5][j];
    float l6 = s_L[rb + 6][j];
    float q0 = s_H[rb    ][j], q1 = s_H[rb + 1][j], q2 = s_H[rb + 2][j];
    float q3 = s_H[rb + 3][j], q4 = s_H[rb + 4][j], q5 = s_H[rb + 5][j];
    float q6 = s_H[rb + 6][j];

    #pragma unroll
    for (int ii = 0; ii < 4; ii++) {
        int i = ib * 4 + ii;             // 0..15

        float LL = h0 * (l2 + l6) + h1c * (l3 + l5) + h2 * l4;
        float LH = g0 * (l0 + l6) + g1 * (l1 + l5) + g2 * (l2 + l4) + g3 * l3;
        float HL = h0 * (q2 + q6) + h1c * (q3 + q5) + h2 * q4;
        float HH = g0 * (q0 + q6) + g1 * (q1 + q5) + g2 * (q2 + q4) + g3 * q3;

        size_t o = imgOff + (size_t)(i0 + i) * 512 + (j0 + j);
        out[o                 ] = LL;
        out[o +     bandStride] = LH;
        out[o + 2 * bandStride] = HL;
        out[o + 3 * bandStride] = HH;

        if (ii < 3) {
            // slide window down by 2 rows
            l0 = l2; l1 = l3; l2 = l4; l3 = l5; l4 = l6;
            q0 = q2; q1 = q3; q2 = q4; q3 = q5; q4 = q6;
            int rn = rb + 7 + 2 * ii;
            l5 = s_L[rn][j]; l6 = s_L[rn + 1][j];
            q5 = s_H[rn][j]; q6 = s_H[rn + 1][j];
        }
    }
}

extern "C" void kernel_launch(void* const* d_in, const int* in_sizes, int n_in,
                              void* d_out, int out_size)
{
    const float* x = (const float*)d_in[0];
    float* out = (float*)d_out;
    dim3 grid(512 / TJ, 512 / TI, 24);   // (8, 32, 24)
    wfb2dec_kernel<<<grid, NTHREADS>>>(x, out);
}